// round 7
// baseline (speedup 1.0000x reference)
#include <cuda_runtime.h>

#define NA_MAX 200000
#define NW 12512               // packed 2-bit type words (16 atoms/word), padded to %4
#define COULOMB 14.399645478425668f
#define PEXP 0.23f
#define A0C 0.4685f

__device__ unsigned int g_type_packed[NW];
__device__ float4 g_pairf4[48];   // 16 pairs x 3 float4: (factor,rc,A/3,B/4) (C,da0,da1,da2) (da3,-,-,-)

// ---------------- prep: pack types to 2-bit + pair table (fp32) ----------------
__global__ void prep_pack(const float* __restrict__ cov, const float* __restrict__ anum,
                          const int* __restrict__ types, int n_atoms) {
    __shared__ unsigned char s_t[4096];
    int base = blockIdx.x * 4096;
    #pragma unroll
    for (int k = 0; k < 16; k++) {
        int a = base + k * 256 + threadIdx.x;
        s_t[k * 256 + threadIdx.x] = (a < n_atoms) ? (unsigned char)types[a] : 0;
    }
    __syncthreads();
    int w = base / 16 + threadIdx.x;
    if (w < NW) {
        unsigned int word = 0;
        #pragma unroll
        for (int j = 0; j < 16; j++)
            word |= ((unsigned int)(s_t[threadIdx.x * 16 + j] & 3u)) << (j * 2);
        g_type_packed[w] = word;
    }

    if (blockIdx.x == 0 && threadIdx.x < 16) {
        int t = threadIdx.x;
        int ti = t >> 2, tj = t & 3;
        float zi = anum[ti], zj = anum[tj];
        float rc = cov[ti] + cov[tj];
        float a  = A0C / (powf(zi, PEXP) + powf(zj, PEXP));
        const float cc[4] = {0.02817f, 0.28022f, 0.50986f, 0.18175f};
        const float dd[4] = {0.20162f, 0.4029f, 0.94229f, 3.1998f};
        float da[4];
        #pragma unroll
        for (int k = 0; k < 4; k++) da[k] = dd[k] / a;
        float factor = COULOMB * zi * zj;

        float phi = 0.f, dphi = 0.f, d2phi = 0.f;
        #pragma unroll
        for (int k = 0; k < 4; k++) {
            float ex = expf(-rc * da[k]);
            phi   += cc[k] * ex;
            dphi  += -cc[k] * da[k] * ex;
            d2phi += cc[k] * da[k] * da[k] * ex;
        }
        float inv_rc = 1.0f / rc;
        float ec   = factor * inv_rc * phi;
        float dec  = factor * inv_rc * (-phi * inv_rc + dphi);
        float d2ec = factor * inv_rc * (d2phi - 2.0f * inv_rc * dphi + 2.0f * phi * inv_rc * inv_rc);

        float A = (-3.0f * dec + rc * d2ec) * inv_rc * inv_rc;
        float B = ( 2.0f * dec - rc * d2ec) * inv_rc * inv_rc * inv_rc;
        float C = -ec + rc * dec * 0.5f - rc * rc * d2ec * (1.0f / 12.0f);

        g_pairf4[t * 3 + 0] = make_float4(factor, rc, A * (1.0f / 3.0f), B * 0.25f);
        g_pairf4[t * 3 + 1] = make_float4(C, da[0], da[1], da[2]);
        g_pairf4[t * 3 + 2] = make_float4(da[3], 0.f, 0.f, 0.f);
    }
}

// ---------------- main edge kernel: SMEM 2-bit type table, 512-thr CTAs, full occupancy ----------------
__global__ void __launch_bounds__(512)
zbl_edges(const float4* __restrict__ rij4, const int4* __restrict__ fa4,
          const int4* __restrict__ sa4, float* __restrict__ out, int nquads) {
    extern __shared__ unsigned char smem_raw[];
    unsigned int* s_types = (unsigned int*)smem_raw;           // NW*4 = 50048 B
    float4*       s_pair  = (float4*)(smem_raw + NW * 4);      // 768 B

    // cooperative table load (int4-vectorized: NW/4 = 3128 int4)
    {
        int4* dst = (int4*)s_types;
        const int4* src = (const int4*)g_type_packed;
        for (int j = threadIdx.x; j < NW / 4; j += 512) dst[j] = src[j];
        if (threadIdx.x < 48) s_pair[threadIdx.x] = g_pairf4[threadIdx.x];
    }
    __syncthreads();

    for (int i = blockIdx.x * blockDim.x + threadIdx.x; i < nquads;
         i += gridDim.x * blockDim.x) {
        float4 r4 = rij4[i];
        int4   f4 = fa4[i];
        int4   s4 = sa4[i];
        const float* rr = &r4.x;
        const int*   ff = &f4.x;
        const int*   ss = &s4.x;
        #pragma unroll
        for (int k = 0; k < 4; k++) {
            float r  = rr[k];
            int   fa = ff[k];
            int   sa = ss[k];
            int ti = (int)((s_types[fa >> 4] >> ((fa & 15) << 1)) & 3u);
            int tj = (int)((s_types[sa >> 4] >> ((sa & 15) << 1)) & 3u);
            int p3 = ((ti << 2) | tj) * 3;
            float4 pa = s_pair[p3];            // factor, rc, A/3, B/4
            if (r <= pa.y) {
                float4 pb = s_pair[p3 + 1];    // C, da0, da1, da2
                float da3 = s_pair[p3 + 2].x;
                float e0 = __expf(-r * pb.y);
                float e1 = __expf(-r * pb.z);
                float e2 = __expf(-r * pb.w);
                float e3 = __expf(-r * da3);
                float phi = 0.02817f * e0 + 0.28022f * e1 + 0.50986f * e2 + 0.18175f * e3;
                float r2 = r * r;
                float e = pa.x * __fdividef(phi, r) + (pa.z + pa.w * r) * r2 * r + pb.x;
                atomicAdd(out + fa, 0.5f * e);
            }
        }
    }
}

// scalar tail (global packed table; E % 4 != 0 safety)
__global__ void zbl_tail(const float* __restrict__ rij, const int* __restrict__ fst,
                         const int* __restrict__ snd, float* __restrict__ out,
                         int start, int nedges) {
    int i = start + blockIdx.x * blockDim.x + threadIdx.x;
    if (i >= nedges) return;
    float r  = rij[i];
    int   fa = fst[i];
    int   sa = snd[i];
    int ti = (int)((g_type_packed[fa >> 4] >> ((fa & 15) << 1)) & 3u);
    int tj = (int)((g_type_packed[sa >> 4] >> ((sa & 15) << 1)) & 3u);
    int p3 = ((ti << 2) | tj) * 3;
    float4 pa = g_pairf4[p3];
    if (r <= pa.y) {
        float4 pb = g_pairf4[p3 + 1];
        float da3 = g_pairf4[p3 + 2].x;
        float e0 = __expf(-r * pb.y);
        float e1 = __expf(-r * pb.z);
        float e2 = __expf(-r * pb.w);
        float e3 = __expf(-r * da3);
        float phi = 0.02817f * e0 + 0.28022f * e1 + 0.50986f * e2 + 0.18175f * e3;
        float r2 = r * r;
        float e = pa.x * __fdividef(phi, r) + (pa.z + pa.w * r) * r2 * r + pb.x;
        atomicAdd(out + fa, 0.5f * e);
    }
}

extern "C" void kernel_launch(void* const* d_in, const int* in_sizes, int n_in,
                              void* d_out, int out_size) {
    const float* rij  = (const float*)d_in[0];
    const float* cov  = (const float*)d_in[1];
    const float* anum = (const float*)d_in[2];
    const int*   fst  = (const int*)d_in[3];
    const int*   snd  = (const int*)d_in[4];
    const int*   typ  = (const int*)d_in[5];
    float* out = (float*)d_out;

    int n_edges = in_sizes[0];
    int n_atoms = in_sizes[5];
    if (n_atoms > NA_MAX) n_atoms = NA_MAX;

    cudaMemsetAsync(out, 0, (size_t)out_size * sizeof(float));

    int pack_blocks = (n_atoms + 4095) / 4096;
    prep_pack<<<pack_blocks, 256>>>(cov, anum, typ, n_atoms);

    const int SMEM_BYTES = NW * 4 + 768;   // 50816 B -> 4 CTAs/SM, 64 warps/SM
    cudaFuncSetAttribute(zbl_edges, cudaFuncAttributeMaxDynamicSharedMemorySize, SMEM_BYTES);

    int nquads = n_edges / 4;
    if (nquads > 0) {
        int grid = (nquads + 511) / 512;
        if (grid > 592) grid = 592;   // 4 x 148 persistent CTAs
        zbl_edges<<<grid, 512, SMEM_BYTES>>>(
            (const float4*)rij, (const int4*)fst, (const int4*)snd, out, nquads);
    }
    int tail_start = nquads * 4;
    int tail = n_edges - tail_start;
    if (tail > 0) {
        zbl_tail<<<(tail + 255) / 256, 256>>>(rij, fst, snd, out, tail_start, n_edges);
    }
}

// round 8
// speedup vs baseline: 1.0779x; 1.0779x over previous
#include <cuda_runtime.h>

#define NA_MAX 200000
#define NW 12512               // packed 2-bit type words (16 atoms/word), padded to %4
#define COULOMB 14.399645478425668f
#define PEXP 0.23f
#define A0C 0.4685f

// -d_k * log2(e), folded so phi terms are exp2f(s * K) = single EX2 + FMA
#define K0 (-0.29087618f)   // -0.20162 * 1.4426950408889634
#define K1 (-0.58126163f)   // -0.4029  * log2e
#define K2 (-1.35943713f)   // -0.94229 * log2e
#define K3 (-4.61633539f)   // -3.1998  * log2e

__device__ unsigned int g_type_packed[NW];
__device__ float  g_rc[16];
__device__ float4 g_pairA[16];   // (factor/2, 1/a, A/6, B/8)
__device__ float2 g_pairB[16];   // (C/2, 0)
__device__ float  g_rcmax;

// ---------------- prep: pack types to 2-bit + slim pair tables (fp32) ----------------
__global__ void prep_pack(const float* __restrict__ cov, const float* __restrict__ anum,
                          const int* __restrict__ types, int n_atoms) {
    __shared__ unsigned char s_t[4096];
    __shared__ float s_rcp[16];
    int base = blockIdx.x * 4096;
    #pragma unroll
    for (int k = 0; k < 16; k++) {
        int a = base + k * 256 + threadIdx.x;
        s_t[k * 256 + threadIdx.x] = (a < n_atoms) ? (unsigned char)types[a] : 0;
    }

    if (blockIdx.x == 0 && threadIdx.x < 16) {
        int t = threadIdx.x;
        int ti = t >> 2, tj = t & 3;
        float zi = anum[ti], zj = anum[tj];
        float rc = cov[ti] + cov[tj];
        float inv_a = (powf(zi, PEXP) + powf(zj, PEXP)) / A0C;  // 1/a
        const float cc[4] = {0.02817f, 0.28022f, 0.50986f, 0.18175f};
        const float dd[4] = {0.20162f, 0.4029f, 0.94229f, 3.1998f};
        float da[4];
        #pragma unroll
        for (int k = 0; k < 4; k++) da[k] = dd[k] * inv_a;
        float factor = COULOMB * zi * zj;

        float phi = 0.f, dphi = 0.f, d2phi = 0.f;
        #pragma unroll
        for (int k = 0; k < 4; k++) {
            float ex = expf(-rc * da[k]);
            phi   += cc[k] * ex;
            dphi  += -cc[k] * da[k] * ex;
            d2phi += cc[k] * da[k] * da[k] * ex;
        }
        float inv_rc = 1.0f / rc;
        float ec   = factor * inv_rc * phi;
        float dec  = factor * inv_rc * (-phi * inv_rc + dphi);
        float d2ec = factor * inv_rc * (d2phi - 2.0f * inv_rc * dphi + 2.0f * phi * inv_rc * inv_rc);

        float A = (-3.0f * dec + rc * d2ec) * inv_rc * inv_rc;
        float B = ( 2.0f * dec - rc * d2ec) * inv_rc * inv_rc * inv_rc;
        float C = -ec + rc * dec * 0.5f - rc * rc * d2ec * (1.0f / 12.0f);

        g_rc[t]    = rc;
        s_rcp[t]   = rc;
        g_pairA[t] = make_float4(factor * 0.5f, inv_a, A * (1.0f / 6.0f), B * 0.125f);
        g_pairB[t] = make_float2(C * 0.5f, 0.f);
    }
    __syncthreads();
    if (blockIdx.x == 0 && threadIdx.x == 0) {
        float m = 0.f;
        #pragma unroll
        for (int k = 0; k < 16; k++) m = fmaxf(m, s_rcp[k]);
        g_rcmax = m;
    }

    int w = base / 16 + threadIdx.x;
    if (w < NW) {
        unsigned int word = 0;
        #pragma unroll
        for (int j = 0; j < 16; j++)
            word |= ((unsigned int)(s_t[threadIdx.x * 16 + j] & 3u)) << (j * 2);
        g_type_packed[w] = word;
    }
}

// ---------------- main edge kernel: early rcmax cull, slim tables, full occupancy ----------------
__global__ void __launch_bounds__(512, 4)
zbl_edges(const float4* __restrict__ rij4, const int4* __restrict__ fa4,
          const int4* __restrict__ sa4, float* __restrict__ out, int nquads) {
    extern __shared__ unsigned char smem_raw[];
    unsigned int* s_types = (unsigned int*)smem_raw;     // NW*4 = 50048 B dynamic
    __shared__ float  s_rcw[16];
    __shared__ float4 s_pA[16];
    __shared__ float2 s_pB[16];

    {
        int4* dst = (int4*)s_types;
        const int4* src = (const int4*)g_type_packed;
        for (int j = threadIdx.x; j < NW / 4; j += 512) dst[j] = src[j];
        if (threadIdx.x < 16) {
            s_rcw[threadIdx.x] = g_rc[threadIdx.x];
            s_pA[threadIdx.x]  = g_pairA[threadIdx.x];
            s_pB[threadIdx.x]  = g_pairB[threadIdx.x];
        }
    }
    __syncthreads();
    const float rcmax = g_rcmax;

    for (int i = blockIdx.x * blockDim.x + threadIdx.x; i < nquads;
         i += gridDim.x * blockDim.x) {
        float4 r4 = rij4[i];
        int4   f4 = fa4[i];
        int4   s4 = sa4[i];
        const float* rr = &r4.x;
        const int*   ff = &f4.x;
        const int*   ss = &s4.x;
        #pragma unroll
        for (int k = 0; k < 4; k++) {
            float r  = rr[k];
            if (r > rcmax) continue;          // no table access at all for ~29% of edges
            int fa = ff[k];
            int sa = ss[k];
            int ti = (int)((s_types[fa >> 4] >> ((fa & 15) << 1)) & 3u);
            int tj = (int)((s_types[sa >> 4] >> ((sa & 15) << 1)) & 3u);
            int p = (ti << 2) | tj;
            float rc = s_rcw[p];
            if (r <= rc) {
                float4 ea = s_pA[p];          // factor/2, 1/a, A/6, B/8
                float2 eb = s_pB[p];          // C/2
                float s = r * ea.y;
                float e0 = exp2f(s * K0);
                float e1 = exp2f(s * K1);
                float e2 = exp2f(s * K2);
                float e3 = exp2f(s * K3);
                float phi = 0.02817f * e0 + 0.28022f * e1 + 0.50986f * e2 + 0.18175f * e3;
                float e = ea.x * __fdividef(phi, r) + (ea.z + ea.w * r) * r * r * r + eb.x;
                atomicAdd(out + fa, e);
            }
        }
    }
}

// scalar tail (global tables; E % 4 != 0 safety)
__global__ void zbl_tail(const float* __restrict__ rij, const int* __restrict__ fst,
                         const int* __restrict__ snd, float* __restrict__ out,
                         int start, int nedges) {
    int i = start + blockIdx.x * blockDim.x + threadIdx.x;
    if (i >= nedges) return;
    float r  = rij[i];
    int   fa = fst[i];
    int   sa = snd[i];
    int ti = (int)((g_type_packed[fa >> 4] >> ((fa & 15) << 1)) & 3u);
    int tj = (int)((g_type_packed[sa >> 4] >> ((sa & 15) << 1)) & 3u);
    int p = (ti << 2) | tj;
    if (r <= g_rc[p]) {
        float4 ea = g_pairA[p];
        float2 eb = g_pairB[p];
        float s = r * ea.y;
        float e0 = exp2f(s * K0);
        float e1 = exp2f(s * K1);
        float e2 = exp2f(s * K2);
        float e3 = exp2f(s * K3);
        float phi = 0.02817f * e0 + 0.28022f * e1 + 0.50986f * e2 + 0.18175f * e3;
        float e = ea.x * __fdividef(phi, r) + (ea.z + ea.w * r) * r * r * r + eb.x;
        atomicAdd(out + fa, e);
    }
}

extern "C" void kernel_launch(void* const* d_in, const int* in_sizes, int n_in,
                              void* d_out, int out_size) {
    const float* rij  = (const float*)d_in[0];
    const float* cov  = (const float*)d_in[1];
    const float* anum = (const float*)d_in[2];
    const int*   fst  = (const int*)d_in[3];
    const int*   snd  = (const int*)d_in[4];
    const int*   typ  = (const int*)d_in[5];
    float* out = (float*)d_out;

    int n_edges = in_sizes[0];
    int n_atoms = in_sizes[5];
    if (n_atoms > NA_MAX) n_atoms = NA_MAX;

    cudaMemsetAsync(out, 0, (size_t)out_size * sizeof(float));

    int pack_blocks = (n_atoms + 4095) / 4096;
    prep_pack<<<pack_blocks, 256>>>(cov, anum, typ, n_atoms);

    const int SMEM_BYTES = NW * 4;   // dynamic part; ~50.5KB total -> 4 CTAs/SM
    cudaFuncSetAttribute(zbl_edges, cudaFuncAttributeMaxDynamicSharedMemorySize, SMEM_BYTES);

    int nquads = n_edges / 4;
    if (nquads > 0) {
        int grid = (nquads + 511) / 512;
        if (grid > 592) grid = 592;   // 4 x 148 persistent CTAs
        zbl_edges<<<grid, 512, SMEM_BYTES>>>(
            (const float4*)rij, (const int4*)fst, (const int4*)snd, out, nquads);
    }
    int tail_start = nquads * 4;
    int tail = n_edges - tail_start;
    if (tail > 0) {
        zbl_tail<<<(tail + 255) / 256, 256>>>(rij, fst, snd, out, tail_start, n_edges);
    }
}

// round 13
// speedup vs baseline: 1.1319x; 1.0500x over previous
#include <cuda_runtime.h>

#define NA_MAX 200000
#define NA_PAD 200704          // NA_MAX padded to 16B multiple for int4 copies
#define COULOMB 14.399645478425668f
#define PEXP 0.23f
#define A0C 0.4685f

// -d_k * log2(e): phi terms become exp2f(s * K) = FMA + EX2
#define K0 (-0.29087618f)
#define K1 (-0.58126163f)
#define K2 (-1.35943713f)
#define K3 (-4.61633539f)

__device__ unsigned char g_type_u8[NA_PAD];
__device__ float4 g_pair0[16];   // (rc, 1/a, factor/2, C/2)
__device__ float2 g_pair1[16];   // (A/6, B/8)
__device__ float  g_rcmax;

// ---------------- prep: u8 type copy + slim pair tables ----------------
__global__ void prep_pack(const float* __restrict__ cov, const float* __restrict__ anum,
                          const int* __restrict__ types, int n_atoms) {
    int gi = blockIdx.x * blockDim.x + threadIdx.x;
    if (gi < NA_PAD) g_type_u8[gi] = (gi < n_atoms) ? (unsigned char)types[gi] : 0;

    if (blockIdx.x == 0 && threadIdx.x < 16) {
        int t = threadIdx.x;
        int ti = t >> 2, tj = t & 3;
        float zi = anum[ti], zj = anum[tj];
        float rc = cov[ti] + cov[tj];
        float inv_a = (powf(zi, PEXP) + powf(zj, PEXP)) / A0C;
        const float cc[4] = {0.02817f, 0.28022f, 0.50986f, 0.18175f};
        const float dd[4] = {0.20162f, 0.4029f, 0.94229f, 3.1998f};
        float da[4];
        #pragma unroll
        for (int k = 0; k < 4; k++) da[k] = dd[k] * inv_a;
        float factor = COULOMB * zi * zj;

        float phi = 0.f, dphi = 0.f, d2phi = 0.f;
        #pragma unroll
        for (int k = 0; k < 4; k++) {
            float ex = expf(-rc * da[k]);
            phi   += cc[k] * ex;
            dphi  += -cc[k] * da[k] * ex;
            d2phi += cc[k] * da[k] * da[k] * ex;
        }
        float inv_rc = 1.0f / rc;
        float ec   = factor * inv_rc * phi;
        float dec  = factor * inv_rc * (-phi * inv_rc + dphi);
        float d2ec = factor * inv_rc * (d2phi - 2.0f * inv_rc * dphi + 2.0f * phi * inv_rc * inv_rc);

        float A = (-3.0f * dec + rc * d2ec) * inv_rc * inv_rc;
        float B = ( 2.0f * dec - rc * d2ec) * inv_rc * inv_rc * inv_rc;
        float C = -ec + rc * dec * 0.5f - rc * rc * d2ec * (1.0f / 12.0f);

        g_pair0[t] = make_float4(rc, inv_a, factor * 0.5f, C * 0.5f);
        g_pair1[t] = make_float2(A * (1.0f / 6.0f), B * 0.125f);

        // rcmax via warp reduction over the 16 active lanes
        float m = rc;
        #pragma unroll
        for (int o = 8; o > 0; o >>= 1)
            m = fmaxf(m, __shfl_xor_sync(0xFFFF, m, o));
        if (t == 0) g_rcmax = m;
    }
}

// ---------------- main edge kernel: u8 SMEM type table (1 CTA/SM, 1024 thr) ----------------
__global__ void __launch_bounds__(1024, 1)
zbl_edges(const float4* __restrict__ rij4, const int4* __restrict__ fa4,
          const int4* __restrict__ sa4, float* __restrict__ out, int nquads) {
    extern __shared__ unsigned char smem_raw[];
    unsigned char* s_types = smem_raw;                       // NA_PAD bytes
    __shared__ float4 s_p0[16];
    __shared__ float2 s_p1[16];

    {
        int4* dst = (int4*)s_types;
        const int4* src = (const int4*)g_type_u8;
        for (int j = threadIdx.x; j < NA_PAD / 16; j += 1024) dst[j] = src[j];
        if (threadIdx.x < 16) {
            s_p0[threadIdx.x] = g_pair0[threadIdx.x];
            s_p1[threadIdx.x] = g_pair1[threadIdx.x];
        }
    }
    __syncthreads();
    const float rcmax = g_rcmax;

    for (int i = blockIdx.x * blockDim.x + threadIdx.x; i < nquads;
         i += gridDim.x * blockDim.x) {
        float4 r4 = rij4[i];
        int4   f4 = fa4[i];
        int4   s4 = sa4[i];
        const float* rr = &r4.x;
        const int*   ff = &f4.x;
        const int*   ss = &s4.x;
        #pragma unroll
        for (int k = 0; k < 4; k++) {
            float r = rr[k];
            if (r > rcmax) continue;               // ~29%: zero table traffic
            int fa = ff[k];
            int p  = ((int)s_types[fa] << 2) | (int)s_types[ss[k]];
            float4 t0 = s_p0[p];                   // rc, 1/a, factor/2, C/2
            if (r <= t0.x) {
                float2 t1 = s_p1[p];               // A/6, B/8
                float s = r * t0.y;
                float e0 = exp2f(s * K0);
                float e1 = exp2f(s * K1);
                float e2 = exp2f(s * K2);
                float e3 = exp2f(s * K3);
                float phi = 0.02817f * e0 + 0.28022f * e1 + 0.50986f * e2 + 0.18175f * e3;
                float e = t0.z * __fdividef(phi, r) + (t1.x + t1.y * r) * r * r * r + t0.w;
                atomicAdd(out + fa, e);
            }
        }
    }
}

// scalar tail (global tables; E % 4 != 0 safety)
__global__ void zbl_tail(const float* __restrict__ rij, const int* __restrict__ fst,
                         const int* __restrict__ snd, float* __restrict__ out,
                         int start, int nedges) {
    int i = start + blockIdx.x * blockDim.x + threadIdx.x;
    if (i >= nedges) return;
    float r  = rij[i];
    int   fa = fst[i];
    int p = ((int)g_type_u8[fa] << 2) | (int)g_type_u8[snd[i]];
    float4 t0 = g_pair0[p];
    if (r <= t0.x) {
        float2 t1 = g_pair1[p];
        float s = r * t0.y;
        float e0 = exp2f(s * K0);
        float e1 = exp2f(s * K1);
        float e2 = exp2f(s * K2);
        float e3 = exp2f(s * K3);
        float phi = 0.02817f * e0 + 0.28022f * e1 + 0.50986f * e2 + 0.18175f * e3;
        float e = t0.z * __fdividef(phi, r) + (t1.x + t1.y * r) * r * r * r + t0.w;
        atomicAdd(out + fa, e);
    }
}

extern "C" void kernel_launch(void* const* d_in, const int* in_sizes, int n_in,
                              void* d_out, int out_size) {
    const float* rij  = (const float*)d_in[0];
    const float* cov  = (const float*)d_in[1];
    const float* anum = (const float*)d_in[2];
    const int*   fst  = (const int*)d_in[3];
    const int*   snd  = (const int*)d_in[4];
    const int*   typ  = (const int*)d_in[5];
    float* out = (float*)d_out;

    int n_edges = in_sizes[0];
    int n_atoms = in_sizes[5];
    if (n_atoms > NA_MAX) n_atoms = NA_MAX;

    cudaMemsetAsync(out, 0, (size_t)out_size * sizeof(float));

    prep_pack<<<(NA_PAD + 255) / 256, 256>>>(cov, anum, typ, n_atoms);

    const int SMEM_BYTES = NA_PAD;   // 200704 B dynamic -> 1 CTA/SM
    cudaFuncSetAttribute(zbl_edges, cudaFuncAttributeMaxDynamicSharedMemorySize, SMEM_BYTES);

    int nquads = n_edges / 4;
    if (nquads > 0) {
        int grid = (nquads + 1023) / 1024;
        if (grid > 148) grid = 148;   // persistent, 1 CTA/SM
        zbl_edges<<<grid, 1024, SMEM_BYTES>>>(
            (const float4*)rij, (const int4*)fst, (const int4*)snd, out, nquads);
    }
    int tail_start = nquads * 4;
    int tail = n_edges - tail_start;
    if (tail > 0) {
        zbl_tail<<<(tail + 255) / 256, 256>>>(rij, fst, snd, out, tail_start, n_edges);
    }
}